// round 14
// baseline (speedup 1.0000x reference)
#include <cuda_runtime.h>
#include <cuda_fp16.h>
#include <math.h>
#include <stdint.h>

// Problem constants (fixed shapes)
#define N_NODES 100000
#define DIM     128
#define NEDGE   600000
#define NREL    5
#define NCOLS   2304          // 128 lin_skip + 256 film_skip + 5*(128 lins + 256 films)
#define NCOLSW  2432          // + 128 cols for linear1_w (final projection)
#define NBINS   (N_NODES * NREL)
#define NBLK_SCAN ((NBINS + 1023) / 1024)   // 489
#define NCT     18            // column tiles in main GEMM

// ---------------- scratch (device globals; no allocation allowed) ----------
__device__ __half   g_C[(size_t)N_NODES * NCOLS]; // fused node-GEMM output (fp16)
__device__ __half   g_Wh[(size_t)NCOLSW * DIM];   // W^T fp16: [c][k]
__device__ float    g_biasv[NCOLSW];              // packed bias
__device__ int      g_cnt[NBINS];                 // per (dst, rel) edge count
__device__ int      g_off[NBINS + 1];             // CSR offsets by (dst, rel)
__device__ int      g_fill[NBINS];                // scatter cursors
__device__ int      g_bsum[512];                  // scan block sums
__device__ int      g_elist[NEDGE];               // src ids, (dst,rel)-sorted

// ---------------- PTX helpers (base PTX only; no 'a' features) -------------
__device__ __forceinline__ uint32_t smem_u32(const void* p) {
    uint32_t a;
    asm("{ .reg .u64 t; cvta.to.shared.u64 t, %1; cvt.u32.u64 %0, t; }"
        : "=r"(a) : "l"(p));
    return a;
}
__device__ __forceinline__ void ldsm_x4(uint32_t (&r)[4], uint32_t addr) {
    asm volatile("ldmatrix.sync.aligned.m8n8.x4.shared.b16 {%0,%1,%2,%3}, [%4];"
                 : "=r"(r[0]), "=r"(r[1]), "=r"(r[2]), "=r"(r[3]) : "r"(addr));
}
__device__ __forceinline__ void mma16816(float (&d)[4], const uint32_t (&a)[4],
                                         const uint32_t (&b)[2]) {
    asm volatile(
        "mma.sync.aligned.m16n8k16.row.col.f32.f16.f16.f32 "
        "{%0,%1,%2,%3}, {%4,%5,%6,%7}, {%8,%9}, {%0,%1,%2,%3};"
        : "+f"(d[0]), "+f"(d[1]), "+f"(d[2]), "+f"(d[3])
        : "r"(a[0]), "r"(a[1]), "r"(a[2]), "r"(a[3]), "r"(b[0]), "r"(b[1]));
}
__device__ __forceinline__ uint32_t pack2h(__half a, __half b) {
    __half2 t = __halves2half2(a, b);
    return *reinterpret_cast<uint32_t*>(&t);
}
__device__ __forceinline__ void cp_async16(uint32_t dst, const void* src) {
    asm volatile("cp.async.cg.shared.global [%0], [%1], 16;"
                 :: "r"(dst), "l"(src) : "memory");
}
__device__ __forceinline__ void cp_commit() {
    asm volatile("cp.async.commit_group;" ::: "memory");
}
template <int N>
__device__ __forceinline__ void cp_wait() {
    asm volatile("cp.async.wait_group %0;" :: "n"(N) : "memory");
}

// ---------------- prep kernels ----------------------------------------------
__global__ void pack_wt_kernel(const float* __restrict__ lin_skip_w,
                               const float* __restrict__ film_skip_w,
                               const float* __restrict__ lins_w,
                               const float* __restrict__ films_w,
                               const float* __restrict__ films_b,
                               const float* __restrict__ linear1_w,
                               const float* __restrict__ linear1_b)
{
    int idx = blockIdx.x * blockDim.x + threadIdx.x;   // over NCOLSW*128
    if (idx < NCOLSW * DIM) {
        int c = idx / DIM;
        int k = idx % DIM;
        float v;
        if (c < 128) {
            v = lin_skip_w[k * 128 + c];
        } else if (c < 384) {
            v = film_skip_w[k * 256 + (c - 128)];
        } else if (c < NCOLS) {
            int r  = (c - 384) / 384;
            int cc = (c - 384) % 384;
            if (cc < 128) v = lins_w[((size_t)r * 128 + k) * 128 + cc];
            else          v = films_w[((size_t)r * 128 + k) * 256 + (cc - 128)];
        } else {
            v = linear1_w[k * 128 + (c - NCOLS)];
        }
        g_Wh[idx] = __float2half_rn(v);
    }
    if (idx < NCOLSW) {
        float b = 0.0f;
        if (idx >= 384 && idx < NCOLS) {
            int r  = (idx - 384) / 384;
            int cc = (idx - 384) % 384;
            if (cc >= 128) b = films_b[r * 256 + (cc - 128)];
        } else if (idx >= NCOLS) {
            b = linear1_b[idx - NCOLS];
        }
        g_biasv[idx] = b;
    }
}

__global__ void zero_kernel()
{
    int i = blockIdx.x * blockDim.x + threadIdx.x;
    if (i < NBINS) { g_cnt[i] = 0; g_fill[i] = 0; }
}

__global__ void cnt_kernel(const int* __restrict__ ei, const int* __restrict__ et)
{
    int e = blockIdx.x * blockDim.x + threadIdx.x;
    if (e < NEDGE) {
        int dst = ei[NEDGE + e];
        int r   = et[e];
        atomicAdd(&g_cnt[dst * NREL + r], 1);
    }
}

// ---- 3-phase parallel exclusive scan over g_cnt ----
__global__ void __launch_bounds__(1024)
scan1_kernel()
{
    __shared__ int wsum[32];
    int tid  = threadIdx.x;
    int lane = tid & 31;
    int wid  = tid >> 5;
    int idx  = blockIdx.x * 1024 + tid;
    int v = (idx < NBINS) ? g_cnt[idx] : 0;
    int orig = v;
#pragma unroll
    for (int o = 1; o < 32; o <<= 1) {
        int t = __shfl_up_sync(0xFFFFFFFF, v, o);
        if (lane >= o) v += t;
    }
    if (lane == 31) wsum[wid] = v;
    __syncthreads();
    if (wid == 0) {
        int s = wsum[lane];
#pragma unroll
        for (int o = 1; o < 32; o <<= 1) {
            int t = __shfl_up_sync(0xFFFFFFFF, s, o);
            if (lane >= o) s += t;
        }
        wsum[lane] = s;
    }
    __syncthreads();
    int winc = (wid > 0) ? wsum[wid - 1] : 0;
    if (idx < NBINS) g_off[idx] = winc + (v - orig);
    if (tid == 1023) g_bsum[blockIdx.x] = winc + v;
}

__global__ void __launch_bounds__(512)
scan2_kernel()
{
    __shared__ int wsum[16];
    int tid  = threadIdx.x;
    int lane = tid & 31;
    int wid  = tid >> 5;
    int v = (tid < NBLK_SCAN) ? g_bsum[tid] : 0;
    int orig = v;
#pragma unroll
    for (int o = 1; o < 32; o <<= 1) {
        int t = __shfl_up_sync(0xFFFFFFFF, v, o);
        if (lane >= o) v += t;
    }
    if (lane == 31) wsum[wid] = v;
    __syncthreads();
    if (wid == 0 && lane < 16) {
        int s = wsum[lane];
#pragma unroll
        for (int o = 1; o < 16; o <<= 1) {
            int t = __shfl_up_sync(0xFFFF, s, o);
            if (lane >= o) s += t;
        }
        wsum[lane] = s;
    }
    __syncthreads();
    int winc = (wid > 0) ? wsum[wid - 1] : 0;
    if (tid < NBLK_SCAN) g_bsum[tid] = winc + (v - orig);
}

__global__ void __launch_bounds__(1024)
scan3_kernel()
{
    int idx = blockIdx.x * 1024 + threadIdx.x;
    if (idx < NBINS) g_off[idx] += g_bsum[blockIdx.x];
    if (idx == 0) g_off[NBINS] = NEDGE;
}

__global__ void scatter_kernel(const int* __restrict__ ei, const int* __restrict__ et)
{
    int e = blockIdx.x * blockDim.x + threadIdx.x;
    if (e >= NEDGE) return;
    int src = ei[e];
    int dst = ei[NEDGE + e];
    int r   = et[e];
    int bin = dst * NREL + r;
    int pos = g_off[bin] + atomicAdd(&g_fill[bin], 1);
    g_elist[pos] = src;
}

// ---------------- persistent-A main GEMM -------------------------------------
// 782 CTAs x 256 threads (8 warps, 64x32 warp tiles). A staged once from fp32
// x (converted to fp16 in the staging loop); loop 18 col tiles of W with
// cp.async double-buffered B. SMEM: A + 2xB = 104448 B -> 2 CTAs/SM.
#define RSTRIDE 272
#define SA_SZ   (128 * RSTRIDE)

__global__ void __launch_bounds__(256, 2)
main_gemm_kernel(const float* __restrict__ Xf,
                 const __half* __restrict__ W,
                 const float* __restrict__ bias,
                 __half* __restrict__ Cout, int M)
{
    extern __shared__ char smem[];
    uint32_t sb = smem_u32(smem);

    int tid  = threadIdx.x;
    int wid  = tid >> 5;
    int lane = tid & 31;
    int rowBase = blockIdx.x * 128;

    // ---- stage A once: fp32 -> fp16 ----
    for (int i = tid; i < 128 * 16; i += 256) {
        int row = i >> 4, ch = i & 15;
        int grow = rowBase + row;
        uint4 uh = make_uint4(0, 0, 0, 0);
        if (grow < M) {
            float4 f0 = *(const float4*)(Xf + (size_t)grow * DIM + ch * 8);
            float4 f1 = *(const float4*)(Xf + (size_t)grow * DIM + ch * 8 + 4);
            uh.x = pack2h(__float2half_rn(f0.x), __float2half_rn(f0.y));
            uh.y = pack2h(__float2half_rn(f0.z), __float2half_rn(f0.w));
            uh.z = pack2h(__float2half_rn(f1.x), __float2half_rn(f1.y));
            uh.w = pack2h(__float2half_rn(f1.z), __float2half_rn(f1.w));
        }
        *(uint4*)(smem + row * RSTRIDE + ch * 16) = uh;
    }
    // ---- issue B(0) ----
    {
        uint32_t bufBase = sb + SA_SZ;
        for (int i = tid; i < 128 * 16; i += 256) {
            int row = i >> 4, ch = i & 15;
            cp_async16(bufBase + row * RSTRIDE + ch * 16,
                       W + (size_t)row * DIM + ch * 8);
        }
        cp_commit();
    }

    // 8 warps: 2m x 4n grid of 64x32 warp tiles
    int mBase = (wid >> 2) * 64;
    int nBase = (wid & 3) * 32;

    uint32_t aAddr = sb + (uint32_t)(mBase + (lane & 15)) * RSTRIDE
                   + (uint32_t)((lane >> 4) << 3) * 2;
    uint32_t bLaneOff = (uint32_t)(nBase + (((lane >> 4) & 1) << 3) + (lane & 7)) * RSTRIDE
                      + (uint32_t)(((lane >> 3) & 1) << 3) * 2;

    for (int t = 0; t < NCT; ++t) {
        if (t + 1 < NCT) {
            uint32_t bufBase = sb + SA_SZ + ((t + 1) & 1) * SA_SZ;
            const __half* wsrc = W + (size_t)(t + 1) * 128 * DIM;
            for (int i = tid; i < 128 * 16; i += 256) {
                int row = i >> 4, ch = i & 15;
                cp_async16(bufBase + row * RSTRIDE + ch * 16,
                           wsrc + (size_t)row * DIM + ch * 8);
            }
            cp_commit();
            cp_wait<1>();
        } else {
            cp_wait<0>();
        }
        __syncthreads();

        uint32_t bAddr = sb + SA_SZ + (t & 1) * SA_SZ + bLaneOff;

        float acc[4][4][4];
#pragma unroll
        for (int i = 0; i < 4; ++i)
#pragma unroll
            for (int j = 0; j < 4; ++j)
#pragma unroll
                for (int q = 0; q < 4; ++q) acc[i][j][q] = 0.0f;

#pragma unroll
        for (int ks = 0; ks < 8; ++ks) {
            uint32_t b[4][2];
#pragma unroll
            for (int jj = 0; jj < 2; ++jj) {
                uint32_t r[4];
                ldsm_x4(r, bAddr + jj * 16 * RSTRIDE + ks * 32);
                b[2 * jj][0] = r[0]; b[2 * jj][1] = r[1];
                b[2 * jj + 1][0] = r[2]; b[2 * jj + 1][1] = r[3];
            }
            uint32_t a[4][4];
#pragma unroll
            for (int i = 0; i < 4; ++i)
                ldsm_x4(a[i], aAddr + i * 16 * RSTRIDE + ks * 32);
#pragma unroll
            for (int i = 0; i < 4; ++i)
#pragma unroll
                for (int j = 0; j < 4; ++j)
                    mma16816(acc[i][j], a[i], b[j]);
        }

        int colBase = t * 128;
#pragma unroll
        for (int i = 0; i < 4; ++i) {
            int row0 = rowBase + mBase + i * 16 + (lane >> 2);
#pragma unroll
            for (int h = 0; h < 2; ++h) {
                int grow = row0 + h * 8;
                if (grow >= M) continue;
                __half* crow = Cout + (size_t)grow * NCOLS + colBase;
#pragma unroll
                for (int j = 0; j < 4; ++j) {
                    int c = nBase + j * 8 + ((lane & 3) << 1);
                    float vx = acc[i][j][h * 2 + 0] + bias[colBase + c];
                    float vy = acc[i][j][h * 2 + 1] + bias[colBase + c + 1];
                    *(uint32_t*)(crow + c) =
                        pack2h(__float2half_rn(vx), __float2half_rn(vy));
                }
            }
        }
        __syncthreads();
    }
}

// ---------------- fused aggregation + GELU + final projection ---------------
// CTA = 128 dst rows, 256 threads (8 warps).
// Phase 1: warp w aggregates dsts [w*16, w*16+16): skip + binned CSR messages,
//          exact GELU, fp16 into SMEM A tile.
// Phase 2: stage linear1 W tile, 64x32-warp-tile MMA, fp32 store to out.
__global__ void __launch_bounds__(256, 2)
agg_proj_kernel(const __half* __restrict__ W,
                const float* __restrict__ bias,
                float* __restrict__ Cout, int M)
{
    extern __shared__ char smem[];
    uint32_t sb = smem_u32(smem);

    int tid  = threadIdx.x;
    int wid  = tid >> 5;
    int lane = tid & 31;
    int rowBase = blockIdx.x * 128;
    int j = lane << 2;   // 4 cols per lane

    // ---- phase 1: aggregation into SMEM A tile ----
    for (int s = 0; s < 16; ++s) {
        int localRow = wid * 16 + s;
        int d = rowBase + localRow;
        float4 acc = make_float4(0.f, 0.f, 0.f, 0.f);
        if (d < M) {
            const __half* base = &g_C[(size_t)d * NCOLS];
            __half2 l01 = *(const __half2*)(base + j);
            __half2 l23 = *(const __half2*)(base + j + 2);
            __half2 b01 = *(const __half2*)(base + 128 + j);
            __half2 b23 = *(const __half2*)(base + 128 + j + 2);
            __half2 s01 = *(const __half2*)(base + 256 + j);
            __half2 s23 = *(const __half2*)(base + 256 + j + 2);
            float2 lf0 = __half22float2(l01), lf1 = __half22float2(l23);
            float2 bf0 = __half22float2(b01), bf1 = __half22float2(b23);
            float2 gf0 = __half22float2(s01), gf1 = __half22float2(s23);
            acc.x = fmaxf(gf0.x * lf0.x + bf0.x, 0.0f);
            acc.y = fmaxf(gf0.y * lf0.y + bf0.y, 0.0f);
            acc.z = fmaxf(gf1.x * lf1.x + bf1.x, 0.0f);
            acc.w = fmaxf(gf1.y * lf1.y + bf1.y, 0.0f);

#pragma unroll
            for (int r = 0; r < NREL; ++r) {
                int begin = g_off[d * NREL + r];
                int end   = g_off[d * NREL + r + 1];
                if (begin == end) continue;
                const __half* db = base + 384 + r * 384 + 128;
                __half2 eb01 = *(const __half2*)(db + j);
                __half2 eb23 = *(const __half2*)(db + j + 2);
                __half2 eg01 = *(const __half2*)(db + 128 + j);
                __half2 eg23 = *(const __half2*)(db + 128 + j + 2);
                float2 ebf0 = __half22float2(eb01), ebf1 = __half22float2(eb23);
                float2 egf0 = __half22float2(eg01), egf1 = __half22float2(eg23);
                float inv = 1.0f / (float)(end - begin);
                float4 racc = make_float4(0.f, 0.f, 0.f, 0.f);
                const size_t xlOff = 384 + (size_t)r * 384;
                for (int e = begin; e < end; ++e) {
                    int src = g_elist[e];
                    const __half* cb = &g_C[(size_t)src * NCOLS + xlOff];
                    __half2 x01 = *(const __half2*)(cb + j);
                    __half2 x23 = *(const __half2*)(cb + j + 2);
                    float2 xf0 = __half22float2(x01), xf1 = __half22float2(x23);
                    racc.x += fmaxf(egf0.x * xf0.x + ebf0.x, 0.0f);
                    racc.y += fmaxf(egf0.y * xf0.y + ebf0.y, 0.0f);
                    racc.z += fmaxf(egf1.x * xf1.x + ebf1.x, 0.0f);
                    racc.w += fmaxf(egf1.y * xf1.y + ebf1.y, 0.0f);
                }
                acc.x += racc.x * inv;
                acc.y += racc.y * inv;
                acc.z += racc.z * inv;
                acc.w += racc.w * inv;
            }

            const float kk = 0.70710678118654752f;
            acc.x = 0.5f * acc.x * (1.0f + erff(acc.x * kk));
            acc.y = 0.5f * acc.y * (1.0f + erff(acc.y * kk));
            acc.z = 0.5f * acc.z * (1.0f + erff(acc.z * kk));
            acc.w = 0.5f * acc.w * (1.0f + erff(acc.w * kk));
        }
        uint2 hv;
        hv.x = pack2h(__float2half_rn(acc.x), __float2half_rn(acc.y));
        hv.y = pack2h(__float2half_rn(acc.z), __float2half_rn(acc.w));
        *(uint2*)(smem + localRow * RSTRIDE + j * 2) = hv;
    }

    // ---- stage B (linear1 W^T rows) ----
    const uint32_t sB = SA_SZ;
    for (int i = tid; i < 128 * 16; i += 256) {
        int row = i >> 4, ch = i & 15;
        int gc = NCOLS + row;
        *(uint4*)(smem + sB + row * RSTRIDE + ch * 16) =
            *(const uint4*)(W + (size_t)gc * DIM + ch * 8);
    }
    __syncthreads();

    // ---- phase 2: MMA (8 warps, 64x32 warp tiles) ----
    int mBase = (wid >> 2) * 64;
    int nBase = (wid & 3) * 32;

    float acc[4][4][4];
#pragma unroll
    for (int i = 0; i < 4; ++i)
#pragma unroll
        for (int jj = 0; jj < 4; ++jj)
#pragma unroll
            for (int q = 0; q < 4; ++q) acc[i][jj][q] = 0.0f;

    uint32_t aAddr = sb + (uint32_t)(mBase + (lane & 15)) * RSTRIDE
                   + (uint32_t)((lane >> 4) << 3) * 2;
    uint32_t bAddr = sb + sB
                   + (uint32_t)(nBase + (((lane >> 4) & 1) << 3) + (lane & 7)) * RSTRIDE
                   + (uint32_t)(((lane >> 3) & 1) << 3) * 2;

#pragma unroll
    for (int ks = 0; ks < 8; ++ks) {
        uint32_t b[4][2];
#pragma unroll
        for (int jj = 0; jj < 2; ++jj) {
            uint32_t r[4];
            ldsm_x4(r, bAddr + jj * 16 * RSTRIDE + ks * 32);
            b[2 * jj][0] = r[0]; b[2 * jj][1] = r[1];
            b[2 * jj + 1][0] = r[2]; b[2 * jj + 1][1] = r[3];
        }
        uint32_t a[4][4];
#pragma unroll
        for (int i = 0; i < 4; ++i)
            ldsm_x4(a[i], aAddr + i * 16 * RSTRIDE + ks * 32);
#pragma unroll
        for (int i = 0; i < 4; ++i)
#pragma unroll
            for (int jj = 0; jj < 4; ++jj)
                mma16816(acc[i][jj], a[i], b[jj]);
    }

#pragma unroll
    for (int i = 0; i < 4; ++i) {
        int row0 = rowBase + mBase + i * 16 + (lane >> 2);
#pragma unroll
        for (int h = 0; h < 2; ++h) {
            int grow = row0 + h * 8;
            if (grow >= M) continue;
            float* crow = Cout + (size_t)grow * 128;
#pragma unroll
            for (int jj = 0; jj < 4; ++jj) {
                int c = nBase + jj * 8 + ((lane & 3) << 1);
                float2 v2;
                v2.x = acc[i][jj][h * 2 + 0] + bias[NCOLS + c];
                v2.y = acc[i][jj][h * 2 + 1] + bias[NCOLS + c + 1];
                *(float2*)(crow + c) = v2;
            }
        }
    }
}

// ---------------- launch ------------------------------------------------------
extern "C" void kernel_launch(void* const* d_in, const int* in_sizes, int n_in,
                              void* d_out, int out_size)
{
    const float* x           = (const float*)d_in[0];
    const int*   ei          = (const int*)d_in[1];
    const int*   et          = (const int*)d_in[2];
    const float* lin_skip_w  = (const float*)d_in[3];
    const float* film_skip_w = (const float*)d_in[4];
    const float* lins_w      = (const float*)d_in[5];
    const float* films_w     = (const float*)d_in[6];
    const float* films_b     = (const float*)d_in[7];
    const float* linear1_w   = (const float*)d_in[8];
    const float* linear1_b   = (const float*)d_in[9];
    float*       out         = (float*)d_out;

    void *pC, *pWh, *pBias;
    cudaGetSymbolAddress(&pC,   g_C);
    cudaGetSymbolAddress(&pWh,  g_Wh);
    cudaGetSymbolAddress(&pBias, g_biasv);

    const int SMEM_MAIN = 3 * SA_SZ;   // 104448
    const int SMEM_FUSE = 2 * SA_SZ;   // 69632
    cudaFuncSetAttribute((const void*)main_gemm_kernel,
                         cudaFuncAttributeMaxDynamicSharedMemorySize, SMEM_MAIN);
    cudaFuncSetAttribute((const void*)agg_proj_kernel,
                         cudaFuncAttributeMaxDynamicSharedMemorySize, SMEM_FUSE);

    // 1. prep: pack W^T fp16 + bias (incl. linear1)
    pack_wt_kernel<<<(NCOLSW * DIM + 255) / 256, 256>>>(
        lin_skip_w, film_skip_w, lins_w, films_w, films_b, linear1_w, linear1_b);

    // 2. edge indexing: counts -> parallel scan -> (dst,rel)-sorted src list
    zero_kernel<<<(NBINS + 255) / 256, 256>>>();
    cnt_kernel<<<(NEDGE + 255) / 256, 256>>>(ei, et);
    scan1_kernel<<<NBLK_SCAN, 1024>>>();
    scan2_kernel<<<1, 512>>>();
    scan3_kernel<<<NBLK_SCAN, 1024>>>();
    scatter_kernel<<<(NEDGE + 255) / 256, 256>>>(ei, et);

    // 3. main GEMM (persistent A from fp32 x, cp.async double-buffered B)
    main_gemm_kernel<<<(N_NODES + 127) / 128, 256, SMEM_MAIN>>>(
        x, (const __half*)pWh, (const float*)pBias, (__half*)pC, N_NODES);

    // 4. fused aggregation + GELU + final projection
    agg_proj_kernel<<<(N_NODES + 127) / 128, 256, SMEM_FUSE>>>(
        (const __half*)pWh, (const float*)pBias, out, N_NODES);
}

// round 15
// speedup vs baseline: 1.3020x; 1.3020x over previous
#include <cuda_runtime.h>
#include <cuda_fp16.h>
#include <math.h>
#include <stdint.h>

// Problem constants (fixed shapes)
#define N_NODES 100000
#define DIM     128
#define NEDGE   600000
#define NREL    5
#define NCOLS   2304          // 128 lin_skip + 256 film_skip + 5*(128 lins + 256 films)
#define NCOLSW  2432          // + 128 cols for linear1_w (final projection)
#define NBINS   (N_NODES * NREL)
#define NBLK_SCAN ((NBINS + 1023) / 1024)   // 489
#define NCT     18            // column tiles in main GEMM

// ---------------- scratch (device globals; no allocation allowed) ----------
__device__ __half   g_C[(size_t)N_NODES * NCOLS]; // fused node-GEMM output (fp16)
__device__ __half   g_xh[(size_t)N_NODES * DIM];  // gelu(out) fp16 (agg -> proj)
__device__ __half   g_Wh[(size_t)NCOLSW * DIM];   // W^T fp16: [c][k]
__device__ float    g_biasv[NCOLSW];              // packed bias
__device__ int      g_cnt[NBINS];                 // per (dst, rel) edge count
__device__ int      g_off[NBINS + 1];             // CSR offsets by (dst, rel)
__device__ int      g_fill[NBINS];                // scatter cursors
__device__ int      g_bsum[512];                  // scan block sums
__device__ int      g_elist[NEDGE];               // src ids, (dst,rel)-sorted

// ---------------- PTX helpers (base PTX only; no 'a' features) -------------
__device__ __forceinline__ uint32_t smem_u32(const void* p) {
    uint32_t a;
    asm("{ .reg .u64 t; cvta.to.shared.u64 t, %1; cvt.u32.u64 %0, t; }"
        : "=r"(a) : "l"(p));
    return a;
}
__device__ __forceinline__ void ldsm_x4(uint32_t (&r)[4], uint32_t addr) {
    asm volatile("ldmatrix.sync.aligned.m8n8.x4.shared.b16 {%0,%1,%2,%3}, [%4];"
                 : "=r"(r[0]), "=r"(r[1]), "=r"(r[2]), "=r"(r[3]) : "r"(addr));
}
__device__ __forceinline__ void mma16816(float (&d)[4], const uint32_t (&a)[4],
                                         const uint32_t (&b)[2]) {
    asm volatile(
        "mma.sync.aligned.m16n8k16.row.col.f32.f16.f16.f32 "
        "{%0,%1,%2,%3}, {%4,%5,%6,%7}, {%8,%9}, {%0,%1,%2,%3};"
        : "+f"(d[0]), "+f"(d[1]), "+f"(d[2]), "+f"(d[3])
        : "r"(a[0]), "r"(a[1]), "r"(a[2]), "r"(a[3]), "r"(b[0]), "r"(b[1]));
}
__device__ __forceinline__ uint32_t pack2h(__half a, __half b) {
    __half2 t = __halves2half2(a, b);
    return *reinterpret_cast<uint32_t*>(&t);
}
__device__ __forceinline__ void cp_async16(uint32_t dst, const void* src) {
    asm volatile("cp.async.cg.shared.global [%0], [%1], 16;"
                 :: "r"(dst), "l"(src) : "memory");
}
__device__ __forceinline__ void cp_commit() {
    asm volatile("cp.async.commit_group;" ::: "memory");
}
template <int N>
__device__ __forceinline__ void cp_wait() {
    asm volatile("cp.async.wait_group %0;" :: "n"(N) : "memory");
}

// ---------------- prep kernels ----------------------------------------------
__global__ void pack_wt_kernel(const float* __restrict__ lin_skip_w,
                               const float* __restrict__ film_skip_w,
                               const float* __restrict__ lins_w,
                               const float* __restrict__ films_w,
                               const float* __restrict__ films_b,
                               const float* __restrict__ linear1_w,
                               const float* __restrict__ linear1_b)
{
    int idx = blockIdx.x * blockDim.x + threadIdx.x;   // over NCOLSW*128
    if (idx < NCOLSW * DIM) {
        int c = idx / DIM;
        int k = idx % DIM;
        float v;
        if (c < 128) {
            v = lin_skip_w[k * 128 + c];
        } else if (c < 384) {
            v = film_skip_w[k * 256 + (c - 128)];
        } else if (c < NCOLS) {
            int r  = (c - 384) / 384;
            int cc = (c - 384) % 384;
            if (cc < 128) v = lins_w[((size_t)r * 128 + k) * 128 + cc];
            else          v = films_w[((size_t)r * 128 + k) * 256 + (cc - 128)];
        } else {
            v = linear1_w[k * 128 + (c - NCOLS)];
        }
        g_Wh[idx] = __float2half_rn(v);
    }
    if (idx < NCOLSW) {
        float b = 0.0f;
        if (idx >= 384 && idx < NCOLS) {
            int r  = (idx - 384) / 384;
            int cc = (idx - 384) % 384;
            if (cc >= 128) b = films_b[r * 256 + (cc - 128)];
        } else if (idx >= NCOLS) {
            b = linear1_b[idx - NCOLS];
        }
        g_biasv[idx] = b;
    }
}

__global__ void zero_kernel()
{
    int i = blockIdx.x * blockDim.x + threadIdx.x;
    if (i < NBINS) { g_cnt[i] = 0; g_fill[i] = 0; }
}

__global__ void cnt_kernel(const int* __restrict__ ei, const int* __restrict__ et)
{
    int e = blockIdx.x * blockDim.x + threadIdx.x;
    if (e < NEDGE) {
        int dst = ei[NEDGE + e];
        int r   = et[e];
        atomicAdd(&g_cnt[dst * NREL + r], 1);
    }
}

// ---- 3-phase parallel exclusive scan over g_cnt ----
__global__ void __launch_bounds__(1024)
scan1_kernel()
{
    __shared__ int wsum[32];
    int tid  = threadIdx.x;
    int lane = tid & 31;
    int wid  = tid >> 5;
    int idx  = blockIdx.x * 1024 + tid;
    int v = (idx < NBINS) ? g_cnt[idx] : 0;
    int orig = v;
#pragma unroll
    for (int o = 1; o < 32; o <<= 1) {
        int t = __shfl_up_sync(0xFFFFFFFF, v, o);
        if (lane >= o) v += t;
    }
    if (lane == 31) wsum[wid] = v;
    __syncthreads();
    if (wid == 0) {
        int s = wsum[lane];
#pragma unroll
        for (int o = 1; o < 32; o <<= 1) {
            int t = __shfl_up_sync(0xFFFFFFFF, s, o);
            if (lane >= o) s += t;
        }
        wsum[lane] = s;
    }
    __syncthreads();
    int winc = (wid > 0) ? wsum[wid - 1] : 0;
    if (idx < NBINS) g_off[idx] = winc + (v - orig);
    if (tid == 1023) g_bsum[blockIdx.x] = winc + v;
}

__global__ void __launch_bounds__(512)
scan2_kernel()
{
    __shared__ int wsum[16];
    int tid  = threadIdx.x;
    int lane = tid & 31;
    int wid  = tid >> 5;
    int v = (tid < NBLK_SCAN) ? g_bsum[tid] : 0;
    int orig = v;
#pragma unroll
    for (int o = 1; o < 32; o <<= 1) {
        int t = __shfl_up_sync(0xFFFFFFFF, v, o);
        if (lane >= o) v += t;
    }
    if (lane == 31) wsum[wid] = v;
    __syncthreads();
    if (wid == 0 && lane < 16) {
        int s = wsum[lane];
#pragma unroll
        for (int o = 1; o < 16; o <<= 1) {
            int t = __shfl_up_sync(0xFFFF, s, o);
            if (lane >= o) s += t;
        }
        wsum[lane] = s;
    }
    __syncthreads();
    int winc = (wid > 0) ? wsum[wid - 1] : 0;
    if (tid < NBLK_SCAN) g_bsum[tid] = winc + (v - orig);
}

__global__ void __launch_bounds__(1024)
scan3_kernel()
{
    int idx = blockIdx.x * 1024 + threadIdx.x;
    if (idx < NBINS) g_off[idx] += g_bsum[blockIdx.x];
    if (idx == 0) g_off[NBINS] = NEDGE;
}

__global__ void scatter_kernel(const int* __restrict__ ei, const int* __restrict__ et)
{
    int e = blockIdx.x * blockDim.x + threadIdx.x;
    if (e >= NEDGE) return;
    int src = ei[e];
    int dst = ei[NEDGE + e];
    int r   = et[e];
    int bin = dst * NREL + r;
    int pos = g_off[bin] + atomicAdd(&g_fill[bin], 1);
    g_elist[pos] = src;
}

// ---------------- persistent-A main GEMM -------------------------------------
// 782 CTAs x 256 threads (8 warps, 64x32 warp tiles). A staged once from fp32
// x (fp16 convert fused into the one-time staging); loop 18 col tiles of W
// with cp.async double-buffered B. SMEM: A + 2xB = 104448 B -> 2 CTAs/SM.
#define RSTRIDE 272
#define SA_SZ   (128 * RSTRIDE)

__global__ void __launch_bounds__(256, 2)
main_gemm_kernel(const float* __restrict__ Xf,
                 const __half* __restrict__ W,
                 const float* __restrict__ bias,
                 __half* __restrict__ Cout, int M)
{
    extern __shared__ char smem[];
    uint32_t sb = smem_u32(smem);

    int tid  = threadIdx.x;
    int wid  = tid >> 5;
    int lane = tid & 31;
    int rowBase = blockIdx.x * 128;

    // ---- stage A once: fp32 -> fp16 ----
    for (int i = tid; i < 128 * 16; i += 256) {
        int row = i >> 4, ch = i & 15;
        int grow = rowBase + row;
        uint4 uh = make_uint4(0, 0, 0, 0);
        if (grow < M) {
            float4 f0 = *(const float4*)(Xf + (size_t)grow * DIM + ch * 8);
            float4 f1 = *(const float4*)(Xf + (size_t)grow * DIM + ch * 8 + 4);
            uh.x = pack2h(__float2half_rn(f0.x), __float2half_rn(f0.y));
            uh.y = pack2h(__float2half_rn(f0.z), __float2half_rn(f0.w));
            uh.z = pack2h(__float2half_rn(f1.x), __float2half_rn(f1.y));
            uh.w = pack2h(__float2half_rn(f1.z), __float2half_rn(f1.w));
        }
        *(uint4*)(smem + row * RSTRIDE + ch * 16) = uh;
    }
    // ---- issue B(0) ----
    {
        uint32_t bufBase = sb + SA_SZ;
        for (int i = tid; i < 128 * 16; i += 256) {
            int row = i >> 4, ch = i & 15;
            cp_async16(bufBase + row * RSTRIDE + ch * 16,
                       W + (size_t)row * DIM + ch * 8);
        }
        cp_commit();
    }

    // 8 warps: 2m x 4n grid of 64x32 warp tiles
    int mBase = (wid >> 2) * 64;
    int nBase = (wid & 3) * 32;

    uint32_t aAddr = sb + (uint32_t)(mBase + (lane & 15)) * RSTRIDE
                   + (uint32_t)((lane >> 4) << 3) * 2;
    uint32_t bLaneOff = (uint32_t)(nBase + (((lane >> 4) & 1) << 3) + (lane & 7)) * RSTRIDE
                      + (uint32_t)(((lane >> 3) & 1) << 3) * 2;

    for (int t = 0; t < NCT; ++t) {
        if (t + 1 < NCT) {
            uint32_t bufBase = sb + SA_SZ + ((t + 1) & 1) * SA_SZ;
            const __half* wsrc = W + (size_t)(t + 1) * 128 * DIM;
            for (int i = tid; i < 128 * 16; i += 256) {
                int row = i >> 4, ch = i & 15;
                cp_async16(bufBase + row * RSTRIDE + ch * 16,
                           wsrc + (size_t)row * DIM + ch * 8);
            }
            cp_commit();
            cp_wait<1>();
        } else {
            cp_wait<0>();
        }
        __syncthreads();

        uint32_t bAddr = sb + SA_SZ + (t & 1) * SA_SZ + bLaneOff;

        float acc[4][4][4];
#pragma unroll
        for (int i = 0; i < 4; ++i)
#pragma unroll
            for (int j = 0; j < 4; ++j)
#pragma unroll
                for (int q = 0; q < 4; ++q) acc[i][j][q] = 0.0f;

#pragma unroll
        for (int ks = 0; ks < 8; ++ks) {
            uint32_t b[4][2];
#pragma unroll
            for (int jj = 0; jj < 2; ++jj) {
                uint32_t r[4];
                ldsm_x4(r, bAddr + jj * 16 * RSTRIDE + ks * 32);
                b[2 * jj][0] = r[0]; b[2 * jj][1] = r[1];
                b[2 * jj + 1][0] = r[2]; b[2 * jj + 1][1] = r[3];
            }
            uint32_t a[4][4];
#pragma unroll
            for (int i = 0; i < 4; ++i)
                ldsm_x4(a[i], aAddr + i * 16 * RSTRIDE + ks * 32);
#pragma unroll
            for (int i = 0; i < 4; ++i)
#pragma unroll
                for (int j = 0; j < 4; ++j)
                    mma16816(acc[i][j], a[i], b[j]);
        }

        int colBase = t * 128;
#pragma unroll
        for (int i = 0; i < 4; ++i) {
            int row0 = rowBase + mBase + i * 16 + (lane >> 2);
#pragma unroll
            for (int h = 0; h < 2; ++h) {
                int grow = row0 + h * 8;
                if (grow >= M) continue;
                __half* crow = Cout + (size_t)grow * NCOLS + colBase;
#pragma unroll
                for (int j = 0; j < 4; ++j) {
                    int c = nBase + j * 8 + ((lane & 3) << 1);
                    float vx = acc[i][j][h * 2 + 0] + bias[colBase + c];
                    float vy = acc[i][j][h * 2 + 1] + bias[colBase + c + 1];
                    *(uint32_t*)(crow + c) =
                        pack2h(__float2half_rn(vx), __float2half_rn(vy));
                }
            }
        }
        __syncthreads();
    }
}

// ---------------- simple GEMM for the final projection -----------------------
__global__ void __launch_bounds__(512, 2)
proj_gemm_kernel(const __half* __restrict__ Ah,
                 const __half* __restrict__ W,
                 const float* __restrict__ bias,
                 float* __restrict__ Cout, int M)
{
    extern __shared__ char smem[];
    uint32_t sb = smem_u32(smem);

    int tid  = threadIdx.x;
    int wid  = tid >> 5;
    int lane = tid & 31;
    int rowBase = blockIdx.x * 128;
    const int colBase = NCOLS;   // linear1 block in g_Wh/bias

    const uint32_t sB = SA_SZ;

    for (int i = tid; i < 128 * 16; i += 512) {
        int row = i >> 4, ch = i & 15;
        int grow = rowBase + row;
        uint4 v = make_uint4(0, 0, 0, 0);
        if (grow < M)
            v = *(const uint4*)(Ah + (size_t)grow * DIM + ch * 8);
        *(uint4*)(smem + row * RSTRIDE + ch * 16) = v;
    }
    for (int i = tid; i < 128 * 16; i += 512) {
        int row = i >> 4, ch = i & 15;
        int gc = colBase + row;
        *(uint4*)(smem + sB + row * RSTRIDE + ch * 16) =
            *(const uint4*)(W + (size_t)gc * DIM + ch * 8);
    }
    __syncthreads();

    int mBase = (wid >> 2) * 32;
    int nBase = (wid & 3) * 32;

    float acc[2][4][4];
#pragma unroll
    for (int i = 0; i < 2; ++i)
#pragma unroll
        for (int j = 0; j < 4; ++j)
#pragma unroll
            for (int q = 0; q < 4; ++q) acc[i][j][q] = 0.0f;

    uint32_t aAddr = sb + (uint32_t)(mBase + (lane & 15)) * RSTRIDE
                   + (uint32_t)((lane >> 4) << 3) * 2;
    uint32_t bAddr = sb + sB
                   + (uint32_t)(nBase + (((lane >> 4) & 1) << 3) + (lane & 7)) * RSTRIDE
                   + (uint32_t)(((lane >> 3) & 1) << 3) * 2;

#pragma unroll
    for (int ks = 0; ks < 8; ++ks) {
        uint32_t b[4][2];
#pragma unroll
        for (int jj = 0; jj < 2; ++jj) {
            uint32_t r[4];
            ldsm_x4(r, bAddr + jj * 16 * RSTRIDE + ks * 32);
            b[2 * jj][0] = r[0]; b[2 * jj][1] = r[1];
            b[2 * jj + 1][0] = r[2]; b[2 * jj + 1][1] = r[3];
        }
        uint32_t a[2][4];
#pragma unroll
        for (int i = 0; i < 2; ++i)
            ldsm_x4(a[i], aAddr + i * 16 * RSTRIDE + ks * 32);
#pragma unroll
        for (int i = 0; i < 2; ++i)
#pragma unroll
            for (int j = 0; j < 4; ++j)
                mma16816(acc[i][j], a[i], b[j]);
    }

#pragma unroll
    for (int i = 0; i < 2; ++i) {
        int row0 = rowBase + mBase + i * 16 + (lane >> 2);
#pragma unroll
        for (int h = 0; h < 2; ++h) {
            int grow = row0 + h * 8;
            if (grow >= M) continue;
            float* crow = Cout + (size_t)grow * 128;
#pragma unroll
            for (int j = 0; j < 4; ++j) {
                int c = nBase + j * 8 + ((lane & 3) << 1);
                float2 v2;
                v2.x = acc[i][j][h * 2 + 0] + bias[colBase + c];
                v2.y = acc[i][j][h * 2 + 1] + bias[colBase + c + 1];
                *(float2*)(crow + c) = v2;
            }
        }
    }
}

// ---------------- aggregation: one warp per dst, binned by relation ---------
__global__ void __launch_bounds__(256)
agg_kernel()
{
    int gwarp = (blockIdx.x * blockDim.x + threadIdx.x) >> 5;
    int lane  = threadIdx.x & 31;
    if (gwarp >= N_NODES) return;
    int d = gwarp;
    int j = lane << 2;   // 4 cols per lane

    const __half* base = &g_C[(size_t)d * NCOLS];

    __half2 l01 = *(const __half2*)(base + j);
    __half2 l23 = *(const __half2*)(base + j + 2);
    __half2 b01 = *(const __half2*)(base + 128 + j);
    __half2 b23 = *(const __half2*)(base + 128 + j + 2);
    __half2 s01 = *(const __half2*)(base + 256 + j);
    __half2 s23 = *(const __half2*)(base + 256 + j + 2);
    float2 lf0 = __half22float2(l01), lf1 = __half22float2(l23);
    float2 bf0 = __half22float2(b01), bf1 = __half22float2(b23);
    float2 gf0 = __half22float2(s01), gf1 = __half22float2(s23);
    float4 acc;
    acc.x = fmaxf(gf0.x * lf0.x + bf0.x, 0.0f);
    acc.y = fmaxf(gf0.y * lf0.y + bf0.y, 0.0f);
    acc.z = fmaxf(gf1.x * lf1.x + bf1.x, 0.0f);
    acc.w = fmaxf(gf1.y * lf1.y + bf1.y, 0.0f);

#pragma unroll
    for (int r = 0; r < NREL; ++r) {
        int begin = g_off[d * NREL + r];
        int end   = g_off[d * NREL + r + 1];
        if (begin == end) continue;
        const __half* db = base + 384 + r * 384 + 128;
        __half2 eb01 = *(const __half2*)(db + j);
        __half2 eb23 = *(const __half2*)(db + j + 2);
        __half2 eg01 = *(const __half2*)(db + 128 + j);
        __half2 eg23 = *(const __half2*)(db + 128 + j + 2);
        float2 ebf0 = __half22float2(eb01), ebf1 = __half22float2(eb23);
        float2 egf0 = __half22float2(eg01), egf1 = __half22float2(eg23);
        float inv = 1.0f / (float)(end - begin);
        float4 racc = make_float4(0.f, 0.f, 0.f, 0.f);
        const size_t xlOff = 384 + (size_t)r * 384;
        for (int e = begin; e < end; ++e) {
            int src = g_elist[e];
            const __half* cb = &g_C[(size_t)src * NCOLS + xlOff];
            __half2 x01 = *(const __half2*)(cb + j);
            __half2 x23 = *(const __half2*)(cb + j + 2);
            float2 xf0 = __half22float2(x01), xf1 = __half22float2(x23);
            racc.x += fmaxf(egf0.x * xf0.x + ebf0.x, 0.0f);
            racc.y += fmaxf(egf0.y * xf0.y + ebf0.y, 0.0f);
            racc.z += fmaxf(egf1.x * xf1.x + ebf1.x, 0.0f);
            racc.w += fmaxf(egf1.y * xf1.y + ebf1.y, 0.0f);
        }
        acc.x += racc.x * inv;
        acc.y += racc.y * inv;
        acc.z += racc.z * inv;
        acc.w += racc.w * inv;
    }

    const float kk = 0.70710678118654752f;
    acc.x = 0.5f * acc.x * (1.0f + erff(acc.x * kk));
    acc.y = 0.5f * acc.y * (1.0f + erff(acc.y * kk));
    acc.z = 0.5f * acc.z * (1.0f + erff(acc.z * kk));
    acc.w = 0.5f * acc.w * (1.0f + erff(acc.w * kk));
    uint2 hv;
    hv.x = pack2h(__float2half_rn(acc.x), __float2half_rn(acc.y));
    hv.y = pack2h(__float2half_rn(acc.z), __float2half_rn(acc.w));
    *reinterpret_cast<uint2*>(&g_xh[(size_t)d * DIM + j]) = hv;
}

// ---------------- launch ------------------------------------------------------
extern "C" void kernel_launch(void* const* d_in, const int* in_sizes, int n_in,
                              void* d_out, int out_size)
{
    const float* x           = (const float*)d_in[0];
    const int*   ei          = (const int*)d_in[1];
    const int*   et          = (const int*)d_in[2];
    const float* lin_skip_w  = (const float*)d_in[3];
    const float* film_skip_w = (const float*)d_in[4];
    const float* lins_w      = (const float*)d_in[5];
    const float* films_w     = (const float*)d_in[6];
    const float* films_b     = (const float*)d_in[7];
    const float* linear1_w   = (const float*)d_in[8];
    const float* linear1_b   = (const float*)d_in[9];
    float*       out         = (float*)d_out;

    void *pC, *pXh, *pWh, *pBias;
    cudaGetSymbolAddress(&pC,   g_C);
    cudaGetSymbolAddress(&pXh,  g_xh);
    cudaGetSymbolAddress(&pWh,  g_Wh);
    cudaGetSymbolAddress(&pBias, g_biasv);

    const int SMEM_MAIN = 3 * SA_SZ;   // 104448
    const int SMEM_PROJ = 2 * SA_SZ;   // 69632
    cudaFuncSetAttribute((const void*)main_gemm_kernel,
                         cudaFuncAttributeMaxDynamicSharedMemorySize, SMEM_MAIN);
    cudaFuncSetAttribute((const void*)proj_gemm_kernel,
                         cudaFuncAttributeMaxDynamicSharedMemorySize, SMEM_PROJ);

    // 1. prep: pack W^T fp16 + bias (incl. linear1)
    pack_wt_kernel<<<(NCOLSW * DIM + 255) / 256, 256>>>(
        lin_skip_w, film_skip_w, lins_w, films_w, films_b, linear1_w, linear1_b);

    // 2. edge indexing: counts -> parallel scan -> (dst,rel)-sorted src list
    zero_kernel<<<(NBINS + 255) / 256, 256>>>();
    cnt_kernel<<<(NEDGE + 255) / 256, 256>>>(ei, et);
    scan1_kernel<<<NBLK_SCAN, 1024>>>();
    scan2_kernel<<<1, 512>>>();
    scan3_kernel<<<NBLK_SCAN, 1024>>>();
    scatter_kernel<<<(NEDGE + 255) / 256, 256>>>(ei, et);

    // 3. main GEMM (persistent A from fp32 x, cp.async double-buffered B)
    main_gemm_kernel<<<(N_NODES + 127) / 128, 256, SMEM_MAIN>>>(
        x, (const __half*)pWh, (const float*)pBias, (__half*)pC, N_NODES);

    // 4. aggregation (skip + messages + GELU), atomics-free -> g_xh fp16
    {
        int warps_per_block = 256 / 32;
        int blocks = (N_NODES + warps_per_block - 1) / warps_per_block;
        agg_kernel<<<blocks, 256>>>();
    }

    // 5. final projection: out = gelu(out) @ linear1_w + linear1_b (fp32 out)
    proj_gemm_kernel<<<(N_NODES + 127) / 128, 512, SMEM_PROJ>>>(
        (const __half*)pXh, (const __half*)pWh, (const float*)pBias,
        out, N_NODES);
}

// round 16
// speedup vs baseline: 1.3492x; 1.0362x over previous
#include <cuda_runtime.h>
#include <cuda_fp16.h>
#include <math.h>
#include <stdint.h>

// Problem constants (fixed shapes)
#define N_NODES 100000
#define DIM     128
#define NEDGE   600000
#define NREL    5
#define NCOLS   2304          // 128 lin_skip + 256 film_skip + 5*(128 lins + 256 films)
#define NCOLSW  2432          // + 128 cols for linear1_w (final projection)
#define NBINS   (N_NODES * NREL)
#define NBLK_SCAN ((NBINS + 1023) / 1024)   // 489
#define NCT     18            // column tiles in main GEMM

// ---------------- scratch (device globals; no allocation allowed) ----------
__device__ __half   g_C[(size_t)N_NODES * NCOLS]; // fused node-GEMM output (fp16)
__device__ __half   g_xh[(size_t)N_NODES * DIM];  // gelu(out) fp16 (agg -> proj)
__device__ __half   g_Wh[(size_t)NCOLSW * DIM];   // W^T fp16: [c][k]
__device__ float    g_biasv[NCOLSW];              // packed bias
__device__ int      g_cnt[NBINS];                 // per (dst, rel) edge count
__device__ int      g_off[NBINS + 1];             // CSR offsets by (dst, rel)
__device__ int      g_fill[NBINS];                // scatter cursors
__device__ int      g_bsum[512];                  // scan block sums
__device__ int      g_elist[NEDGE];               // src ids, (dst,rel)-sorted

// ---------------- PTX helpers (base PTX only; no 'a' features) -------------
__device__ __forceinline__ uint32_t smem_u32(const void* p) {
    uint32_t a;
    asm("{ .reg .u64 t; cvta.to.shared.u64 t, %1; cvt.u32.u64 %0, t; }"
        : "=r"(a) : "l"(p));
    return a;
}
__device__ __forceinline__ void ldsm_x4(uint32_t (&r)[4], uint32_t addr) {
    asm volatile("ldmatrix.sync.aligned.m8n8.x4.shared.b16 {%0,%1,%2,%3}, [%4];"
                 : "=r"(r[0]), "=r"(r[1]), "=r"(r[2]), "=r"(r[3]) : "r"(addr));
}
__device__ __forceinline__ void mma16816(float (&d)[4], const uint32_t (&a)[4],
                                         const uint32_t (&b)[2]) {
    asm volatile(
        "mma.sync.aligned.m16n8k16.row.col.f32.f16.f16.f32 "
        "{%0,%1,%2,%3}, {%4,%5,%6,%7}, {%8,%9}, {%0,%1,%2,%3};"
        : "+f"(d[0]), "+f"(d[1]), "+f"(d[2]), "+f"(d[3])
        : "r"(a[0]), "r"(a[1]), "r"(a[2]), "r"(a[3]), "r"(b[0]), "r"(b[1]));
}
__device__ __forceinline__ uint32_t pack2h(__half a, __half b) {
    __half2 t = __halves2half2(a, b);
    return *reinterpret_cast<uint32_t*>(&t);
}
__device__ __forceinline__ void cp_async16(uint32_t dst, const void* src) {
    asm volatile("cp.async.cg.shared.global [%0], [%1], 16;"
                 :: "r"(dst), "l"(src) : "memory");
}
__device__ __forceinline__ void cp_commit() {
    asm volatile("cp.async.commit_group;" ::: "memory");
}
template <int N>
__device__ __forceinline__ void cp_wait() {
    asm volatile("cp.async.wait_group %0;" :: "n"(N) : "memory");
}

// ---------------- prep kernels ----------------------------------------------
__global__ void pack_wt_kernel(const float* __restrict__ lin_skip_w,
                               const float* __restrict__ film_skip_w,
                               const float* __restrict__ lins_w,
                               const float* __restrict__ films_w,
                               const float* __restrict__ films_b,
                               const float* __restrict__ linear1_w,
                               const float* __restrict__ linear1_b)
{
    int idx = blockIdx.x * blockDim.x + threadIdx.x;   // over NCOLSW*128
    if (idx < NCOLSW * DIM) {
        int c = idx / DIM;
        int k = idx % DIM;
        float v;
        if (c < 128) {
            v = lin_skip_w[k * 128 + c];
        } else if (c < 384) {
            v = film_skip_w[k * 256 + (c - 128)];
        } else if (c < NCOLS) {
            int r  = (c - 384) / 384;
            int cc = (c - 384) % 384;
            if (cc < 128) v = lins_w[((size_t)r * 128 + k) * 128 + cc];
            else          v = films_w[((size_t)r * 128 + k) * 256 + (cc - 128)];
        } else {
            v = linear1_w[k * 128 + (c - NCOLS)];
        }
        g_Wh[idx] = __float2half_rn(v);
    }
    if (idx < NCOLSW) {
        float b = 0.0f;
        if (idx >= 384 && idx < NCOLS) {
            int r  = (idx - 384) / 384;
            int cc = (idx - 384) % 384;
            if (cc >= 128) b = films_b[r * 256 + (cc - 128)];
        } else if (idx >= NCOLS) {
            b = linear1_b[idx - NCOLS];
        }
        g_biasv[idx] = b;
    }
}

__global__ void zero_kernel()
{
    int i = blockIdx.x * blockDim.x + threadIdx.x;
    if (i < NBINS) { g_cnt[i] = 0; g_fill[i] = 0; }
}

__global__ void cnt_kernel(const int* __restrict__ ei, const int* __restrict__ et)
{
    int e = blockIdx.x * blockDim.x + threadIdx.x;
    if (e < NEDGE) {
        int dst = ei[NEDGE + e];
        int r   = et[e];
        atomicAdd(&g_cnt[dst * NREL + r], 1);
    }
}

// ---- 3-phase parallel exclusive scan over g_cnt ----
__global__ void __launch_bounds__(1024)
scan1_kernel()
{
    __shared__ int wsum[32];
    int tid  = threadIdx.x;
    int lane = tid & 31;
    int wid  = tid >> 5;
    int idx  = blockIdx.x * 1024 + tid;
    int v = (idx < NBINS) ? g_cnt[idx] : 0;
    int orig = v;
#pragma unroll
    for (int o = 1; o < 32; o <<= 1) {
        int t = __shfl_up_sync(0xFFFFFFFF, v, o);
        if (lane >= o) v += t;
    }
    if (lane == 31) wsum[wid] = v;
    __syncthreads();
    if (wid == 0) {
        int s = wsum[lane];
#pragma unroll
        for (int o = 1; o < 32; o <<= 1) {
            int t = __shfl_up_sync(0xFFFFFFFF, s, o);
            if (lane >= o) s += t;
        }
        wsum[lane] = s;
    }
    __syncthreads();
    int winc = (wid > 0) ? wsum[wid - 1] : 0;
    if (idx < NBINS) g_off[idx] = winc + (v - orig);
    if (tid == 1023) g_bsum[blockIdx.x] = winc + v;
}

__global__ void __launch_bounds__(512)
scan2_kernel()
{
    __shared__ int wsum[16];
    int tid  = threadIdx.x;
    int lane = tid & 31;
    int wid  = tid >> 5;
    int v = (tid < NBLK_SCAN) ? g_bsum[tid] : 0;
    int orig = v;
#pragma unroll
    for (int o = 1; o < 32; o <<= 1) {
        int t = __shfl_up_sync(0xFFFFFFFF, v, o);
        if (lane >= o) v += t;
    }
    if (lane == 31) wsum[wid] = v;
    __syncthreads();
    if (wid == 0 && lane < 16) {
        int s = wsum[lane];
#pragma unroll
        for (int o = 1; o < 16; o <<= 1) {
            int t = __shfl_up_sync(0xFFFF, s, o);
            if (lane >= o) s += t;
        }
        wsum[lane] = s;
    }
    __syncthreads();
    int winc = (wid > 0) ? wsum[wid - 1] : 0;
    if (tid < NBLK_SCAN) g_bsum[tid] = winc + (v - orig);
}

__global__ void __launch_bounds__(1024)
scan3_kernel()
{
    int idx = blockIdx.x * 1024 + threadIdx.x;
    if (idx < NBINS) g_off[idx] += g_bsum[blockIdx.x];
    if (idx == 0) g_off[NBINS] = NEDGE;
}

__global__ void scatter_kernel(const int* __restrict__ ei, const int* __restrict__ et)
{
    int e = blockIdx.x * blockDim.x + threadIdx.x;
    if (e >= NEDGE) return;
    int src = ei[e];
    int dst = ei[NEDGE + e];
    int r   = et[e];
    int bin = dst * NREL + r;
    int pos = g_off[bin] + atomicAdd(&g_fill[bin], 1);
    g_elist[pos] = src;
}

// ---------------- persistent-A main GEMM -------------------------------------
// 782 CTAs x 256 threads (8 warps, 64x32 warp tiles). A staged once from fp32
// x (fp16 convert fused into the one-time staging); loop 18 col tiles of W
// with cp.async double-buffered B. SMEM: A + 2xB = 104448 B -> 2 CTAs/SM.
#define RSTRIDE 272
#define SA_SZ   (128 * RSTRIDE)

__global__ void __launch_bounds__(256, 2)
main_gemm_kernel(const float* __restrict__ Xf,
                 const __half* __restrict__ W,
                 const float* __restrict__ bias,
                 __half* __restrict__ Cout, int M)
{
    extern __shared__ char smem[];
    uint32_t sb = smem_u32(smem);

    int tid  = threadIdx.x;
    int wid  = tid >> 5;
    int lane = tid & 31;
    int rowBase = blockIdx.x * 128;

    // ---- stage A once: fp32 -> fp16 ----
    for (int i = tid; i < 128 * 16; i += 256) {
        int row = i >> 4, ch = i & 15;
        int grow = rowBase + row;
        uint4 uh = make_uint4(0, 0, 0, 0);
        if (grow < M) {
            float4 f0 = *(const float4*)(Xf + (size_t)grow * DIM + ch * 8);
            float4 f1 = *(const float4*)(Xf + (size_t)grow * DIM + ch * 8 + 4);
            uh.x = pack2h(__float2half_rn(f0.x), __float2half_rn(f0.y));
            uh.y = pack2h(__float2half_rn(f0.z), __float2half_rn(f0.w));
            uh.z = pack2h(__float2half_rn(f1.x), __float2half_rn(f1.y));
            uh.w = pack2h(__float2half_rn(f1.z), __float2half_rn(f1.w));
        }
        *(uint4*)(smem + row * RSTRIDE + ch * 16) = uh;
    }
    // ---- issue B(0) ----
    {
        uint32_t bufBase = sb + SA_SZ;
        for (int i = tid; i < 128 * 16; i += 256) {
            int row = i >> 4, ch = i & 15;
            cp_async16(bufBase + row * RSTRIDE + ch * 16,
                       W + (size_t)row * DIM + ch * 8);
        }
        cp_commit();
    }

    // 8 warps: 2m x 4n grid of 64x32 warp tiles
    int mBase = (wid >> 2) * 64;
    int nBase = (wid & 3) * 32;

    uint32_t aAddr = sb + (uint32_t)(mBase + (lane & 15)) * RSTRIDE
                   + (uint32_t)((lane >> 4) << 3) * 2;
    uint32_t bLaneOff = (uint32_t)(nBase + (((lane >> 4) & 1) << 3) + (lane & 7)) * RSTRIDE
                      + (uint32_t)(((lane >> 3) & 1) << 3) * 2;

    for (int t = 0; t < NCT; ++t) {
        if (t + 1 < NCT) {
            uint32_t bufBase = sb + SA_SZ + ((t + 1) & 1) * SA_SZ;
            const __half* wsrc = W + (size_t)(t + 1) * 128 * DIM;
            for (int i = tid; i < 128 * 16; i += 256) {
                int row = i >> 4, ch = i & 15;
                cp_async16(bufBase + row * RSTRIDE + ch * 16,
                           wsrc + (size_t)row * DIM + ch * 8);
            }
            cp_commit();
            cp_wait<1>();
        } else {
            cp_wait<0>();
        }
        __syncthreads();

        uint32_t bAddr = sb + SA_SZ + (t & 1) * SA_SZ + bLaneOff;

        float acc[4][4][4];
#pragma unroll
        for (int i = 0; i < 4; ++i)
#pragma unroll
            for (int j = 0; j < 4; ++j)
#pragma unroll
                for (int q = 0; q < 4; ++q) acc[i][j][q] = 0.0f;

#pragma unroll
        for (int ks = 0; ks < 8; ++ks) {
            uint32_t b[4][2];
#pragma unroll
            for (int jj = 0; jj < 2; ++jj) {
                uint32_t r[4];
                ldsm_x4(r, bAddr + jj * 16 * RSTRIDE + ks * 32);
                b[2 * jj][0] = r[0]; b[2 * jj][1] = r[1];
                b[2 * jj + 1][0] = r[2]; b[2 * jj + 1][1] = r[3];
            }
            uint32_t a[4][4];
#pragma unroll
            for (int i = 0; i < 4; ++i)
                ldsm_x4(a[i], aAddr + i * 16 * RSTRIDE + ks * 32);
#pragma unroll
            for (int i = 0; i < 4; ++i)
#pragma unroll
                for (int j = 0; j < 4; ++j)
                    mma16816(acc[i][j], a[i], b[j]);
        }

        int colBase = t * 128;
#pragma unroll
        for (int i = 0; i < 4; ++i) {
            int row0 = rowBase + mBase + i * 16 + (lane >> 2);
#pragma unroll
            for (int h = 0; h < 2; ++h) {
                int grow = row0 + h * 8;
                if (grow >= M) continue;
                __half* crow = Cout + (size_t)grow * NCOLS + colBase;
#pragma unroll
                for (int j = 0; j < 4; ++j) {
                    int c = nBase + j * 8 + ((lane & 3) << 1);
                    float vx = acc[i][j][h * 2 + 0] + bias[colBase + c];
                    float vy = acc[i][j][h * 2 + 1] + bias[colBase + c + 1];
                    *(uint32_t*)(crow + c) =
                        pack2h(__float2half_rn(vx), __float2half_rn(vy));
                }
            }
        }
        __syncthreads();
    }
}

// ---------------- simple GEMM for the final projection -----------------------
__global__ void __launch_bounds__(512, 2)
proj_gemm_kernel(const __half* __restrict__ Ah,
                 const __half* __restrict__ W,
                 const float* __restrict__ bias,
                 float* __restrict__ Cout, int M)
{
    extern __shared__ char smem[];
    uint32_t sb = smem_u32(smem);

    int tid  = threadIdx.x;
    int wid  = tid >> 5;
    int lane = tid & 31;
    int rowBase = blockIdx.x * 128;
    const int colBase = NCOLS;   // linear1 block in g_Wh/bias

    const uint32_t sB = SA_SZ;

    for (int i = tid; i < 128 * 16; i += 512) {
        int row = i >> 4, ch = i & 15;
        int grow = rowBase + row;
        uint4 v = make_uint4(0, 0, 0, 0);
        if (grow < M)
            v = *(const uint4*)(Ah + (size_t)grow * DIM + ch * 8);
        *(uint4*)(smem + row * RSTRIDE + ch * 16) = v;
    }
    for (int i = tid; i < 128 * 16; i += 512) {
        int row = i >> 4, ch = i & 15;
        int gc = colBase + row;
        *(uint4*)(smem + sB + row * RSTRIDE + ch * 16) =
            *(const uint4*)(W + (size_t)gc * DIM + ch * 8);
    }
    __syncthreads();

    int mBase = (wid >> 2) * 32;
    int nBase = (wid & 3) * 32;

    float acc[2][4][4];
#pragma unroll
    for (int i = 0; i < 2; ++i)
#pragma unroll
        for (int j = 0; j < 4; ++j)
#pragma unroll
            for (int q = 0; q < 4; ++q) acc[i][j][q] = 0.0f;

    uint32_t aAddr = sb + (uint32_t)(mBase + (lane & 15)) * RSTRIDE
                   + (uint32_t)((lane >> 4) << 3) * 2;
    uint32_t bAddr = sb + sB
                   + (uint32_t)(nBase + (((lane >> 4) & 1) << 3) + (lane & 7)) * RSTRIDE
                   + (uint32_t)(((lane >> 3) & 1) << 3) * 2;

#pragma unroll
    for (int ks = 0; ks < 8; ++ks) {
        uint32_t b[4][2];
#pragma unroll
        for (int jj = 0; jj < 2; ++jj) {
            uint32_t r[4];
            ldsm_x4(r, bAddr + jj * 16 * RSTRIDE + ks * 32);
            b[2 * jj][0] = r[0]; b[2 * jj][1] = r[1];
            b[2 * jj + 1][0] = r[2]; b[2 * jj + 1][1] = r[3];
        }
        uint32_t a[2][4];
#pragma unroll
        for (int i = 0; i < 2; ++i)
            ldsm_x4(a[i], aAddr + i * 16 * RSTRIDE + ks * 32);
#pragma unroll
        for (int i = 0; i < 2; ++i)
#pragma unroll
            for (int j = 0; j < 4; ++j)
                mma16816(acc[i][j], a[i], b[j]);
    }

#pragma unroll
    for (int i = 0; i < 2; ++i) {
        int row0 = rowBase + mBase + i * 16 + (lane >> 2);
#pragma unroll
        for (int h = 0; h < 2; ++h) {
            int grow = row0 + h * 8;
            if (grow >= M) continue;
            float* crow = Cout + (size_t)grow * 128;
#pragma unroll
            for (int j = 0; j < 4; ++j) {
                int c = nBase + j * 8 + ((lane & 3) << 1);
                float2 v2;
                v2.x = acc[i][j][h * 2 + 0] + bias[colBase + c];
                v2.y = acc[i][j][h * 2 + 1] + bias[colBase + c + 1];
                *(float2*)(crow + c) = v2;
            }
        }
    }
}

// ---------------- aggregation: one warp per dst, binned by relation ---------
__global__ void __launch_bounds__(256)
agg_kernel()
{
    int gwarp = (blockIdx.x * blockDim.x + threadIdx.x) >> 5;
    int lane  = threadIdx.x & 31;
    if (gwarp >= N_NODES) return;
    int d = gwarp;
    int j = lane << 2;   // 4 cols per lane

    const __half* base = &g_C[(size_t)d * NCOLS];

    __half2 l01 = *(const __half2*)(base + j);
    __half2 l23 = *(const __half2*)(base + j + 2);
    __half2 b01 = *(const __half2*)(base + 128 + j);
    __half2 b23 = *(const __half2*)(base + 128 + j + 2);
    __half2 s01 = *(const __half2*)(base + 256 + j);
    __half2 s23 = *(const __half2*)(base + 256 + j + 2);
    float2 lf0 = __half22float2(l01), lf1 = __half22float2(l23);
    float2 bf0 = __half22float2(b01), bf1 = __half22float2(b23);
    float2 gf0 = __half22float2(s01), gf1 = __half22float2(s23);
    float4 acc;
    acc.x = fmaxf(gf0.x * lf0.x + bf0.x, 0.0f);
    acc.y = fmaxf(gf0.y * lf0.y + bf0.y, 0.0f);
    acc.z = fmaxf(gf1.x * lf1.x + bf1.x, 0.0f);
    acc.w = fmaxf(gf1.y * lf1.y + bf1.y, 0.0f);

#pragma unroll
    for (int r = 0; r < NREL; ++r) {
        int begin = g_off[d * NREL + r];
        int end   = g_off[d * NREL + r + 1];
        if (begin == end) continue;
        const __half* db = base + 384 + r * 384 + 128;
        __half2 eb01 = *(const __half2*)(db + j);
        __half2 eb23 = *(const __half2*)(db + j + 2);
        __half2 eg01 = *(const __half2*)(db + 128 + j);
        __half2 eg23 = *(const __half2*)(db + 128 + j + 2);
        float2 ebf0 = __half22float2(eb01), ebf1 = __half22float2(eb23);
        float2 egf0 = __half22float2(eg01), egf1 = __half22float2(eg23);
        float inv = 1.0f / (float)(end - begin);
        float4 racc = make_float4(0.f, 0.f, 0.f, 0.f);
        const size_t xlOff = 384 + (size_t)r * 384;
        for (int e = begin; e < end; ++e) {
            int src = g_elist[e];
            const __half* cb = &g_C[(size_t)src * NCOLS + xlOff];
            __half2 x01 = *(const __half2*)(cb + j);
            __half2 x23 = *(const __half2*)(cb + j + 2);
            float2 xf0 = __half22float2(x01), xf1 = __half22float2(x23);
            racc.x += fmaxf(egf0.x * xf0.x + ebf0.x, 0.0f);
            racc.y += fmaxf(egf0.y * xf0.y + ebf0.y, 0.0f);
            racc.z += fmaxf(egf1.x * xf1.x + ebf1.x, 0.0f);
            racc.w += fmaxf(egf1.y * xf1.y + ebf1.y, 0.0f);
        }
        acc.x += racc.x * inv;
        acc.y += racc.y * inv;
        acc.z += racc.z * inv;
        acc.w += racc.w * inv;
    }

    const float kk = 0.70710678118654752f;
    acc.x = 0.5f * acc.x * (1.0f + erff(acc.x * kk));
    acc.y = 0.5f * acc.y * (1.0f + erff(acc.y * kk));
    acc.z = 0.5f * acc.z * (1.0f + erff(acc.z * kk));
    acc.w = 0.5f * acc.w * (1.0f + erff(acc.w * kk));
    uint2 hv;
    hv.x = pack2h(__float2half_rn(acc.x), __float2half_rn(acc.y));
    hv.y = pack2h(__float2half_rn(acc.z), __float2half_rn(acc.w));
    *reinterpret_cast<uint2*>(&g_xh[(size_t)d * DIM + j]) = hv;
}

// ---------------- launch ------------------------------------------------------
extern "C" void kernel_launch(void* const* d_in, const int* in_sizes, int n_in,
                              void* d_out, int out_size)
{
    const float* x           = (const float*)d_in[0];
    const int*   ei          = (const int*)d_in[1];
    const int*   et          = (const int*)d_in[2];
    const float* lin_skip_w  = (const float*)d_in[3];
    const float* film_skip_w = (const float*)d_in[4];
    const float* lins_w      = (const float*)d_in[5];
    const float* films_w     = (const float*)d_in[6];
    const float* films_b     = (const float*)d_in[7];
    const float* linear1_w   = (const float*)d_in[8];
    const float* linear1_b   = (const float*)d_in[9];
    float*       out         = (float*)d_out;

    void *pC, *pXh, *pWh, *pBias;
    cudaGetSymbolAddress(&pC,   g_C);
    cudaGetSymbolAddress(&pXh,  g_xh);
    cudaGetSymbolAddress(&pWh,  g_Wh);
    cudaGetSymbolAddress(&pBias, g_biasv);

    const int SMEM_MAIN = 3 * SA_SZ;   // 104448
    const int SMEM_PROJ = 2 * SA_SZ;   // 69632
    cudaFuncSetAttribute((const void*)main_gemm_kernel,
                         cudaFuncAttributeMaxDynamicSharedMemorySize, SMEM_MAIN);
    cudaFuncSetAttribute((const void*)proj_gemm_kernel,
                         cudaFuncAttributeMaxDynamicSharedMemorySize, SMEM_PROJ);

    // Stream fork: edge indexing runs concurrently with pack_wt + main GEMM.
    // (Streams/events are created per call and intentionally not destroyed —
    //  destroying a stream participating in capture would invalidate it.)
    cudaStream_t s2;
    cudaStreamCreateWithFlags(&s2, cudaStreamNonBlocking);
    cudaEvent_t evFork, evJoin;
    cudaEventCreateWithFlags(&evFork, cudaEventDisableTiming);
    cudaEventCreateWithFlags(&evJoin, cudaEventDisableTiming);

    cudaEventRecord(evFork, 0);
    cudaStreamWaitEvent(s2, evFork, 0);

    // --- branch A (s2): edge indexing chain (needed only by agg) ---
    zero_kernel<<<(NBINS + 255) / 256, 256, 0, s2>>>();
    cnt_kernel<<<(NEDGE + 255) / 256, 256, 0, s2>>>(ei, et);
    scan1_kernel<<<NBLK_SCAN, 1024, 0, s2>>>();
    scan2_kernel<<<1, 512, 0, s2>>>();
    scan3_kernel<<<NBLK_SCAN, 1024, 0, s2>>>();
    scatter_kernel<<<(NEDGE + 255) / 256, 256, 0, s2>>>(ei, et);
    cudaEventRecord(evJoin, s2);

    // --- branch B (default stream): W pack + main GEMM ---
    pack_wt_kernel<<<(NCOLSW * DIM + 255) / 256, 256>>>(
        lin_skip_w, film_skip_w, lins_w, films_w, films_b, linear1_w, linear1_b);
    main_gemm_kernel<<<(N_NODES + 127) / 128, 256, SMEM_MAIN>>>(
        x, (const __half*)pWh, (const float*)pBias, (__half*)pC, N_NODES);

    // join: agg needs both the CSR (branch A) and C (branch B)
    cudaStreamWaitEvent(0, evJoin, 0);

    // 4. aggregation (skip + messages + GELU), atomics-free -> g_xh fp16
    {
        int warps_per_block = 256 / 32;
        int blocks = (N_NODES + warps_per_block - 1) / warps_per_block;
        agg_kernel<<<blocks, 256>>>();
    }

    // 5. final projection: out = gelu(out) @ linear1_w + linear1_b (fp32 out)
    proj_gemm_kernel<<<(N_NODES + 127) / 128, 512, SMEM_PROJ>>>(
        (const __half*)pXh, (const __half*)pWh, (const float*)pBias,
        out, N_NODES);
}

// round 17
// speedup vs baseline: 1.3735x; 1.0181x over previous
#include <cuda_runtime.h>
#include <cuda_fp16.h>
#include <math.h>
#include <stdint.h>

// Problem constants (fixed shapes)
#define N_NODES 100000
#define DIM     128
#define NEDGE   600000
#define NREL    5
#define NCOLS   2304          // 128 lin_skip + 256 film_skip + 5*(128 lins + 256 films)
#define NCOLSW  2432          // + 128 cols for linear1_w (final projection)
#define NBINS   (N_NODES * NREL)
#define NBLK_SCAN ((NBINS + 1023) / 1024)   // 489
#define NCT     18            // column tiles in main GEMM
#define CSPLIT  2             // col-tile groups (gridDim.y)
#define NCT_PER (NCT / CSPLIT)

// ---------------- scratch (device globals; no allocation allowed) ----------
__device__ __half   g_C[(size_t)N_NODES * NCOLS]; // fused node-GEMM output (fp16)
__device__ __half   g_xh[(size_t)N_NODES * DIM];  // gelu(out) fp16 (agg -> proj)
__device__ __half   g_Wh[(size_t)NCOLSW * DIM];   // W^T fp16: [c][k]
__device__ float    g_biasv[NCOLSW];              // packed bias
__device__ int      g_cnt[NBINS];                 // per (dst, rel) edge count
__device__ int      g_off[NBINS + 1];             // CSR offsets by (dst, rel)
__device__ int      g_fill[NBINS];                // scatter cursors
__device__ int      g_bsum[512];                  // scan block sums
__device__ int      g_elist[NEDGE];               // src ids, (dst,rel)-sorted

// ---------------- PTX helpers (base PTX only; no 'a' features) -------------
__device__ __forceinline__ uint32_t smem_u32(const void* p) {
    uint32_t a;
    asm("{ .reg .u64 t; cvta.to.shared.u64 t, %1; cvt.u32.u64 %0, t; }"
        : "=r"(a) : "l"(p));
    return a;
}
__device__ __forceinline__ void ldsm_x4(uint32_t (&r)[4], uint32_t addr) {
    asm volatile("ldmatrix.sync.aligned.m8n8.x4.shared.b16 {%0,%1,%2,%3}, [%4];"
                 : "=r"(r[0]), "=r"(r[1]), "=r"(r[2]), "=r"(r[3]) : "r"(addr));
}
__device__ __forceinline__ void mma16816(float (&d)[4], const uint32_t (&a)[4],
                                         const uint32_t (&b)[2]) {
    asm volatile(
        "mma.sync.aligned.m16n8k16.row.col.f32.f16.f16.f32 "
        "{%0,%1,%2,%3}, {%4,%5,%6,%7}, {%8,%9}, {%0,%1,%2,%3};"
        : "+f"(d[0]), "+f"(d[1]), "+f"(d[2]), "+f"(d[3])
        : "r"(a[0]), "r"(a[1]), "r"(a[2]), "r"(a[3]), "r"(b[0]), "r"(b[1]));
}
__device__ __forceinline__ uint32_t pack2h(__half a, __half b) {
    __half2 t = __halves2half2(a, b);
    return *reinterpret_cast<uint32_t*>(&t);
}
__device__ __forceinline__ void cp_async16(uint32_t dst, const void* src) {
    asm volatile("cp.async.cg.shared.global [%0], [%1], 16;"
                 :: "r"(dst), "l"(src) : "memory");
}
__device__ __forceinline__ void cp_commit() {
    asm volatile("cp.async.commit_group;" ::: "memory");
}
template <int N>
__device__ __forceinline__ void cp_wait() {
    asm volatile("cp.async.wait_group %0;" :: "n"(N) : "memory");
}

// ---------------- prep kernels ----------------------------------------------
__global__ void pack_wt_kernel(const float* __restrict__ lin_skip_w,
                               const float* __restrict__ film_skip_w,
                               const float* __restrict__ lins_w,
                               const float* __restrict__ films_w,
                               const float* __restrict__ films_b,
                               const float* __restrict__ linear1_w,
                               const float* __restrict__ linear1_b)
{
    int idx = blockIdx.x * blockDim.x + threadIdx.x;   // over NCOLSW*128
    if (idx < NCOLSW * DIM) {
        int c = idx / DIM;
        int k = idx % DIM;
        float v;
        if (c < 128) {
            v = lin_skip_w[k * 128 + c];
        } else if (c < 384) {
            v = film_skip_w[k * 256 + (c - 128)];
        } else if (c < NCOLS) {
            int r  = (c - 384) / 384;
            int cc = (c - 384) % 384;
            if (cc < 128) v = lins_w[((size_t)r * 128 + k) * 128 + cc];
            else          v = films_w[((size_t)r * 128 + k) * 256 + (cc - 128)];
        } else {
            v = linear1_w[k * 128 + (c - NCOLS)];
        }
        g_Wh[idx] = __float2half_rn(v);
    }
    if (idx < NCOLSW) {
        float b = 0.0f;
        if (idx >= 384 && idx < NCOLS) {
            int r  = (idx - 384) / 384;
            int cc = (idx - 384) % 384;
            if (cc >= 128) b = films_b[r * 256 + (cc - 128)];
        } else if (idx >= NCOLS) {
            b = linear1_b[idx - NCOLS];
        }
        g_biasv[idx] = b;
    }
}

__global__ void zero_kernel()
{
    int i = blockIdx.x * blockDim.x + threadIdx.x;
    if (i < NBINS) { g_cnt[i] = 0; g_fill[i] = 0; }
}

__global__ void cnt_kernel(const int* __restrict__ ei, const int* __restrict__ et)
{
    int e = blockIdx.x * blockDim.x + threadIdx.x;
    if (e < NEDGE) {
        int dst = ei[NEDGE + e];
        int r   = et[e];
        atomicAdd(&g_cnt[dst * NREL + r], 1);
    }
}

// ---- 3-phase parallel exclusive scan over g_cnt ----
__global__ void __launch_bounds__(1024)
scan1_kernel()
{
    __shared__ int wsum[32];
    int tid  = threadIdx.x;
    int lane = tid & 31;
    int wid  = tid >> 5;
    int idx  = blockIdx.x * 1024 + tid;
    int v = (idx < NBINS) ? g_cnt[idx] : 0;
    int orig = v;
#pragma unroll
    for (int o = 1; o < 32; o <<= 1) {
        int t = __shfl_up_sync(0xFFFFFFFF, v, o);
        if (lane >= o) v += t;
    }
    if (lane == 31) wsum[wid] = v;
    __syncthreads();
    if (wid == 0) {
        int s = wsum[lane];
#pragma unroll
        for (int o = 1; o < 32; o <<= 1) {
            int t = __shfl_up_sync(0xFFFFFFFF, s, o);
            if (lane >= o) s += t;
        }
        wsum[lane] = s;
    }
    __syncthreads();
    int winc = (wid > 0) ? wsum[wid - 1] : 0;
    if (idx < NBINS) g_off[idx] = winc + (v - orig);
    if (tid == 1023) g_bsum[blockIdx.x] = winc + v;
}

__global__ void __launch_bounds__(512)
scan2_kernel()
{
    __shared__ int wsum[16];
    int tid  = threadIdx.x;
    int lane = tid & 31;
    int wid  = tid >> 5;
    int v = (tid < NBLK_SCAN) ? g_bsum[tid] : 0;
    int orig = v;
#pragma unroll
    for (int o = 1; o < 32; o <<= 1) {
        int t = __shfl_up_sync(0xFFFFFFFF, v, o);
        if (lane >= o) v += t;
    }
    if (lane == 31) wsum[wid] = v;
    __syncthreads();
    if (wid == 0 && lane < 16) {
        int s = wsum[lane];
#pragma unroll
        for (int o = 1; o < 16; o <<= 1) {
            int t = __shfl_up_sync(0xFFFF, s, o);
            if (lane >= o) s += t;
        }
        wsum[lane] = s;
    }
    __syncthreads();
    int winc = (wid > 0) ? wsum[wid - 1] : 0;
    if (tid < NBLK_SCAN) g_bsum[tid] = winc + (v - orig);
}

__global__ void __launch_bounds__(1024)
scan3_kernel()
{
    int idx = blockIdx.x * 1024 + threadIdx.x;
    if (idx < NBINS) g_off[idx] += g_bsum[blockIdx.x];
    if (idx == 0) g_off[NBINS] = NEDGE;
}

__global__ void scatter_kernel(const int* __restrict__ ei, const int* __restrict__ et)
{
    int e = blockIdx.x * blockDim.x + threadIdx.x;
    if (e >= NEDGE) return;
    int src = ei[e];
    int dst = ei[NEDGE + e];
    int r   = et[e];
    int bin = dst * NREL + r;
    int pos = g_off[bin] + atomicAdd(&g_fill[bin], 1);
    g_elist[pos] = src;
}

// ---------------- persistent-A main GEMM -------------------------------------
// grid (782, 2) x 256 threads (8 warps, 64x32 warp tiles). Each CTA owns a
// 128-row A tile (staged once, fp32->fp16) and 9 of the 18 col tiles of W
// (cp.async double-buffered). Smaller CTA granularity halves the
// wave-quantization tail. SMEM: A + 2xB = 104448 B -> 2 CTAs/SM.
#define RSTRIDE 272
#define SA_SZ   (128 * RSTRIDE)

__global__ void __launch_bounds__(256, 2)
main_gemm_kernel(const float* __restrict__ Xf,
                 const __half* __restrict__ W,
                 const float* __restrict__ bias,
                 __half* __restrict__ Cout, int M)
{
    extern __shared__ char smem[];
    uint32_t sb = smem_u32(smem);

    int tid  = threadIdx.x;
    int wid  = tid >> 5;
    int lane = tid & 31;
    int rowBase  = blockIdx.x * 128;
    int tileBase = blockIdx.y * NCT_PER;   // first col tile for this CTA

    // ---- stage A once: fp32 -> fp16 ----
    for (int i = tid; i < 128 * 16; i += 256) {
        int row = i >> 4, ch = i & 15;
        int grow = rowBase + row;
        uint4 uh = make_uint4(0, 0, 0, 0);
        if (grow < M) {
            float4 f0 = *(const float4*)(Xf + (size_t)grow * DIM + ch * 8);
            float4 f1 = *(const float4*)(Xf + (size_t)grow * DIM + ch * 8 + 4);
            uh.x = pack2h(__float2half_rn(f0.x), __float2half_rn(f0.y));
            uh.y = pack2h(__float2half_rn(f0.z), __float2half_rn(f0.w));
            uh.z = pack2h(__float2half_rn(f1.x), __float2half_rn(f1.y));
            uh.w = pack2h(__float2half_rn(f1.z), __float2half_rn(f1.w));
        }
        *(uint4*)(smem + row * RSTRIDE + ch * 16) = uh;
    }
    // ---- issue B(tileBase) ----
    {
        uint32_t bufBase = sb + SA_SZ;
        const __half* wsrc = W + (size_t)tileBase * 128 * DIM;
        for (int i = tid; i < 128 * 16; i += 256) {
            int row = i >> 4, ch = i & 15;
            cp_async16(bufBase + row * RSTRIDE + ch * 16,
                       wsrc + (size_t)row * DIM + ch * 8);
        }
        cp_commit();
    }

    // 8 warps: 2m x 4n grid of 64x32 warp tiles
    int mBase = (wid >> 2) * 64;
    int nBase = (wid & 3) * 32;

    uint32_t aAddr = sb + (uint32_t)(mBase + (lane & 15)) * RSTRIDE
                   + (uint32_t)((lane >> 4) << 3) * 2;
    uint32_t bLaneOff = (uint32_t)(nBase + (((lane >> 4) & 1) << 3) + (lane & 7)) * RSTRIDE
                      + (uint32_t)(((lane >> 3) & 1) << 3) * 2;

    for (int t = 0; t < NCT_PER; ++t) {
        if (t + 1 < NCT_PER) {
            uint32_t bufBase = sb + SA_SZ + ((t + 1) & 1) * SA_SZ;
            const __half* wsrc = W + (size_t)(tileBase + t + 1) * 128 * DIM;
            for (int i = tid; i < 128 * 16; i += 256) {
                int row = i >> 4, ch = i & 15;
                cp_async16(bufBase + row * RSTRIDE + ch * 16,
                           wsrc + (size_t)row * DIM + ch * 8);
            }
            cp_commit();
            cp_wait<1>();
        } else {
            cp_wait<0>();
        }
        __syncthreads();

        uint32_t bAddr = sb + SA_SZ + (t & 1) * SA_SZ + bLaneOff;

        float acc[4][4][4];
#pragma unroll
        for (int i = 0; i < 4; ++i)
#pragma unroll
            for (int j = 0; j < 4; ++j)
#pragma unroll
                for (int q = 0; q < 4; ++q) acc[i][j][q] = 0.0f;

#pragma unroll
        for (int ks = 0; ks < 8; ++ks) {
            uint32_t b[4][2];
#pragma unroll
            for (int jj = 0; jj < 2; ++jj) {
                uint32_t r[4];
                ldsm_x4(r, bAddr + jj * 16 * RSTRIDE + ks * 32);
                b[2 * jj][0] = r[0]; b[2 * jj][1] = r[1];
                b[2 * jj + 1][0] = r[2]; b[2 * jj + 1][1] = r[3];
            }
            uint32_t a[4][4];
#pragma unroll
            for (int i = 0; i < 4; ++i)
                ldsm_x4(a[i], aAddr + i * 16 * RSTRIDE + ks * 32);
#pragma unroll
            for (int i = 0; i < 4; ++i)
#pragma unroll
                for (int j = 0; j < 4; ++j)
                    mma16816(acc[i][j], a[i], b[j]);
        }

        int colBase = (tileBase + t) * 128;
#pragma unroll
        for (int i = 0; i < 4; ++i) {
            int row0 = rowBase + mBase + i * 16 + (lane >> 2);
#pragma unroll
            for (int h = 0; h < 2; ++h) {
                int grow = row0 + h * 8;
                if (grow >= M) continue;
                __half* crow = Cout + (size_t)grow * NCOLS + colBase;
#pragma unroll
                for (int j = 0; j < 4; ++j) {
                    int c = nBase + j * 8 + ((lane & 3) << 1);
                    float vx = acc[i][j][h * 2 + 0] + bias[colBase + c];
                    float vy = acc[i][j][h * 2 + 1] + bias[colBase + c + 1];
                    *(uint32_t*)(crow + c) =
                        pack2h(__float2half_rn(vx), __float2half_rn(vy));
                }
            }
        }
        __syncthreads();
    }
}

// ---------------- simple GEMM for the final projection -----------------------
__global__ void __launch_bounds__(512, 2)
proj_gemm_kernel(const __half* __restrict__ Ah,
                 const __half* __restrict__ W,
                 const float* __restrict__ bias,
                 float* __restrict__ Cout, int M)
{
    extern __shared__ char smem[];
    uint32_t sb = smem_u32(smem);

    int tid  = threadIdx.x;
    int wid  = tid >> 5;
    int lane = tid & 31;
    int rowBase = blockIdx.x * 128;
    const int colBase = NCOLS;   // linear1 block in g_Wh/bias

    const uint32_t sB = SA_SZ;

    for (int i = tid; i < 128 * 16; i += 512) {
        int row = i >> 4, ch = i & 15;
        int grow = rowBase + row;
        uint4 v = make_uint4(0, 0, 0, 0);
        if (grow < M)
            v = *(const uint4*)(Ah + (size_t)grow * DIM + ch * 8);
        *(uint4*)(smem + row * RSTRIDE + ch * 16) = v;
    }
    for (int i = tid; i < 128 * 16; i += 512) {
        int row = i >> 4, ch = i & 15;
        int gc = colBase + row;
        *(uint4*)(smem + sB + row * RSTRIDE + ch * 16) =
            *(const uint4*)(W + (size_t)gc * DIM + ch * 8);
    }
    __syncthreads();

    int mBase = (wid >> 2) * 32;
    int nBase = (wid & 3) * 32;

    float acc[2][4][4];
#pragma unroll
    for (int i = 0; i < 2; ++i)
#pragma unroll
        for (int j = 0; j < 4; ++j)
#pragma unroll
            for (int q = 0; q < 4; ++q) acc[i][j][q] = 0.0f;

    uint32_t aAddr = sb + (uint32_t)(mBase + (lane & 15)) * RSTRIDE
                   + (uint32_t)((lane >> 4) << 3) * 2;
    uint32_t bAddr = sb + sB
                   + (uint32_t)(nBase + (((lane >> 4) & 1) << 3) + (lane & 7)) * RSTRIDE
                   + (uint32_t)(((lane >> 3) & 1) << 3) * 2;

#pragma unroll
    for (int ks = 0; ks < 8; ++ks) {
        uint32_t b[4][2];
#pragma unroll
        for (int jj = 0; jj < 2; ++jj) {
            uint32_t r[4];
            ldsm_x4(r, bAddr + jj * 16 * RSTRIDE + ks * 32);
            b[2 * jj][0] = r[0]; b[2 * jj][1] = r[1];
            b[2 * jj + 1][0] = r[2]; b[2 * jj + 1][1] = r[3];
        }
        uint32_t a[2][4];
#pragma unroll
        for (int i = 0; i < 2; ++i)
            ldsm_x4(a[i], aAddr + i * 16 * RSTRIDE + ks * 32);
#pragma unroll
        for (int i = 0; i < 2; ++i)
#pragma unroll
            for (int j = 0; j < 4; ++j)
                mma16816(acc[i][j], a[i], b[j]);
    }

#pragma unroll
    for (int i = 0; i < 2; ++i) {
        int row0 = rowBase + mBase + i * 16 + (lane >> 2);
#pragma unroll
        for (int h = 0; h < 2; ++h) {
            int grow = row0 + h * 8;
            if (grow >= M) continue;
            float* crow = Cout + (size_t)grow * 128;
#pragma unroll
            for (int j = 0; j < 4; ++j) {
                int c = nBase + j * 8 + ((lane & 3) << 1);
                float2 v2;
                v2.x = acc[i][j][h * 2 + 0] + bias[colBase + c];
                v2.y = acc[i][j][h * 2 + 1] + bias[colBase + c + 1];
                *(float2*)(crow + c) = v2;
            }
        }
    }
}

// ---------------- aggregation: one warp per dst, binned by relation ---------
__global__ void __launch_bounds__(256)
agg_kernel()
{
    int gwarp = (blockIdx.x * blockDim.x + threadIdx.x) >> 5;
    int lane  = threadIdx.x & 31;
    if (gwarp >= N_NODES) return;
    int d = gwarp;
    int j = lane << 2;   // 4 cols per lane

    const __half* base = &g_C[(size_t)d * NCOLS];

    __half2 l01 = *(const __half2*)(base + j);
    __half2 l23 = *(const __half2*)(base + j + 2);
    __half2 b01 = *(const __half2*)(base + 128 + j);
    __half2 b23 = *(const __half2*)(base + 128 + j + 2);
    __half2 s01 = *(const __half2*)(base + 256 + j);
    __half2 s23 = *(const __half2*)(base + 256 + j + 2);
    float2 lf0 = __half22float2(l01), lf1 = __half22float2(l23);
    float2 bf0 = __half22float2(b01), bf1 = __half22float2(b23);
    float2 gf0 = __half22float2(s01), gf1 = __half22float2(s23);
    float4 acc;
    acc.x = fmaxf(gf0.x * lf0.x + bf0.x, 0.0f);
    acc.y = fmaxf(gf0.y * lf0.y + bf0.y, 0.0f);
    acc.z = fmaxf(gf1.x * lf1.x + bf1.x, 0.0f);
    acc.w = fmaxf(gf1.y * lf1.y + bf1.y, 0.0f);

#pragma unroll
    for (int r = 0; r < NREL; ++r) {
        int begin = g_off[d * NREL + r];
        int end   = g_off[d * NREL + r + 1];
        if (begin == end) continue;
        const __half* db = base + 384 + r * 384 + 128;
        __half2 eb01 = *(const __half2*)(db + j);
        __half2 eb23 = *(const __half2*)(db + j + 2);
        __half2 eg01 = *(const __half2*)(db + 128 + j);
        __half2 eg23 = *(const __half2*)(db + 128 + j + 2);
        float2 ebf0 = __half22float2(eb01), ebf1 = __half22float2(eb23);
        float2 egf0 = __half22float2(eg01), egf1 = __half22float2(eg23);
        float inv = 1.0f / (float)(end - begin);
        float4 racc = make_float4(0.f, 0.f, 0.f, 0.f);
        const size_t xlOff = 384 + (size_t)r * 384;
        for (int e = begin; e < end; ++e) {
            int src = g_elist[e];
            const __half* cb = &g_C[(size_t)src * NCOLS + xlOff];
            __half2 x01 = *(const __half2*)(cb + j);
            __half2 x23 = *(const __half2*)(cb + j + 2);
            float2 xf0 = __half22float2(x01), xf1 = __half22float2(x23);
            racc.x += fmaxf(egf0.x * xf0.x + ebf0.x, 0.0f);
            racc.y += fmaxf(egf0.y * xf0.y + ebf0.y, 0.0f);
            racc.z += fmaxf(egf1.x * xf1.x + ebf1.x, 0.0f);
            racc.w += fmaxf(egf1.y * xf1.y + ebf1.y, 0.0f);
        }
        acc.x += racc.x * inv;
        acc.y += racc.y * inv;
        acc.z += racc.z * inv;
        acc.w += racc.w * inv;
    }

    const float kk = 0.70710678118654752f;
    acc.x = 0.5f * acc.x * (1.0f + erff(acc.x * kk));
    acc.y = 0.5f * acc.y * (1.0f + erff(acc.y * kk));
    acc.z = 0.5f * acc.z * (1.0f + erff(acc.z * kk));
    acc.w = 0.5f * acc.w * (1.0f + erff(acc.w * kk));
    uint2 hv;
    hv.x = pack2h(__float2half_rn(acc.x), __float2half_rn(acc.y));
    hv.y = pack2h(__float2half_rn(acc.z), __float2half_rn(acc.w));
    *reinterpret_cast<uint2*>(&g_xh[(size_t)d * DIM + j]) = hv;
}

// ---------------- launch ------------------------------------------------------
extern "C" void kernel_launch(void* const* d_in, const int* in_sizes, int n_in,
                              void* d_out, int out_size)
{
    const float* x           = (const float*)d_in[0];
    const int*   ei          = (const int*)d_in[1];
    const int*   et          = (const int*)d_in[2];
    const float* lin_skip_w  = (const float*)d_in[3];
    const float* film_skip_w = (const float*)d_in[4];
    const float* lins_w      = (const float*)d_in[5];
    const float* films_w     = (const float*)d_in[6];
    const float* films_b     = (const float*)d_in[7];
    const float* linear1_w   = (const float*)d_in[8];
    const float* linear1_b   = (const float*)d_in[9];
    float*       out         = (float*)d_out;

    void *pC, *pXh, *pWh, *pBias;
    cudaGetSymbolAddress(&pC,   g_C);
    cudaGetSymbolAddress(&pXh,  g_xh);
    cudaGetSymbolAddress(&pWh,  g_Wh);
    cudaGetSymbolAddress(&pBias, g_biasv);

    const int SMEM_MAIN = 3 * SA_SZ;   // 104448
    const int SMEM_PROJ = 2 * SA_SZ;   // 69632
    cudaFuncSetAttribute((const void*)main_gemm_kernel,
                         cudaFuncAttributeMaxDynamicSharedMemorySize, SMEM_MAIN);
    cudaFuncSetAttribute((const void*)proj_gemm_kernel,
                         cudaFuncAttributeMaxDynamicSharedMemorySize, SMEM_PROJ);

    // Stream fork: edge indexing runs concurrently with pack_wt + main GEMM.
    cudaStream_t s2;
    cudaStreamCreateWithFlags(&s2, cudaStreamNonBlocking);
    cudaEvent_t evFork, evJoin;
    cudaEventCreateWithFlags(&evFork, cudaEventDisableTiming);
    cudaEventCreateWithFlags(&evJoin, cudaEventDisableTiming);

    cudaEventRecord(evFork, 0);
    cudaStreamWaitEvent(s2, evFork, 0);

    // --- branch A (s2): edge indexing chain (needed only by agg) ---
    zero_kernel<<<(NBINS + 255) / 256, 256, 0, s2>>>();
    cnt_kernel<<<(NEDGE + 255) / 256, 256, 0, s2>>>(ei, et);
    scan1_kernel<<<NBLK_SCAN, 1024, 0, s2>>>();
    scan2_kernel<<<1, 512, 0, s2>>>();
    scan3_kernel<<<NBLK_SCAN, 1024, 0, s2>>>();
    scatter_kernel<<<(NEDGE + 255) / 256, 256, 0, s2>>>(ei, et);
    cudaEventRecord(evJoin, s2);

    // --- branch B (default stream): W pack + main GEMM (col-split grid) ---
    pack_wt_kernel<<<(NCOLSW * DIM + 255) / 256, 256>>>(
        lin_skip_w, film_skip_w, lins_w, films_w, films_b, linear1_w, linear1_b);
    {
        dim3 grid((N_NODES + 127) / 128, CSPLIT);
        main_gemm_kernel<<<grid, 256, SMEM_MAIN>>>(
            x, (const __half*)pWh, (const float*)pBias, (__half*)pC, N_NODES);
    }

    // join: agg needs both the CSR (branch A) and C (branch B)
    cudaStreamWaitEvent(0, evJoin, 0);

    // 4. aggregation (skip + messages + GELU), atomics-free -> g_xh fp16
    {
        int warps_per_block = 256 / 32;
        int blocks = (N_NODES + warps_per_block - 1) / warps_per_block;
        agg_kernel<<<blocks, 256>>>();
    }

    // 5. final projection: out = gelu(out) @ linear1_w + linear1_b (fp32 out)
    proj_gemm_kernel<<<(N_NODES + 127) / 128, 512, SMEM_PROJ>>>(
        (const __half*)pXh, (const __half*)pWh, (const float*)pBias,
        out, N_NODES);
}